// round 4
// baseline (speedup 1.0000x reference)
#include <cuda_runtime.h>
#include <math.h>

#define NN      20000
#define NE      500000
#define NGR     64      // graphs
#define NGAUSS  100
#define NLAYER  6
#define FCW     128
#define EMBW    92

#define DELTA     (6.0f/99.0f)
#define INV_DELTA (99.0f/6.0f)
#define COEFF     (-0.5f/(DELTA*DELTA))
#define GW        7

#define GEMM_SMEM ((64*256 + 32*64)*4)
#define P1_SMEM   ((NGAUSS*128 + 128)*4)

// ---------------- scratch (device globals; no allocs allowed) ----------------
__device__ float  g_x[NN*64];
__device__ float  g_PQ[NN*256];
__device__ float  g_Z[NE*128];          // 256 MB edge pre-activation scratch
__device__ float  g_agg[NN*64];
__device__ double g_bn_sum[128];
__device__ double g_bn_ssq[128];
__device__ float  g_ss[256];            // BN scale[128] | shift[128]
__device__ float  g_mol[NGR*64];
__device__ float  g_cnt[NGR];
__device__ float  g_h1[NGR*FCW];
__device__ float  g_h2[NGR*FCW];

// ---------------- helpers ----------------
__device__ __forceinline__ float splusf(float x){
    float e = __expf(-fabsf(x));
    return fmaxf(x, 0.0f) + __logf(1.0f + e);
}
__device__ __forceinline__ float sigmf(float x){
    float e = __expf(-fabsf(x));
    float r = __fdividef(1.0f, 1.0f + e);
    return (x >= 0.0f) ? r : e * r;
}

// ---------------- x = embedding[an] @ nuc_W + nuc_b ----------------
__global__ void nuc_kernel(const int* __restrict__ an, const float* __restrict__ emb,
                           const float* __restrict__ W, const float* __restrict__ b){
    __shared__ float Ws[EMBW*64];
    __shared__ float bs[64];
    for (int i = threadIdx.x; i < EMBW*64; i += blockDim.x) Ws[i] = W[i];
    if (threadIdx.x < 64) bs[threadIdx.x] = b[threadIdx.x];
    __syncthreads();
    int lane = threadIdx.x & 31;
    int warp = (blockIdx.x*blockDim.x + threadIdx.x) >> 5;
    int nw   = (gridDim.x*blockDim.x) >> 5;
    for (int n = warp; n < NN; n += nw){
        const float* er = emb + an[n]*EMBW;
        float a0 = bs[lane], a1 = bs[lane+32];
        #pragma unroll 4
        for (int e = 0; e < EMBW; e++){
            float v = __ldg(er + e);
            a0 = fmaf(v, Ws[e*64 + lane],      a0);
            a1 = fmaf(v, Ws[e*64 + lane + 32], a1);
        }
        g_x[n*64 + lane]      = a0;
        g_x[n*64 + lane + 32] = a1;
    }
}

// ---------------- per-layer: zero agg + BN accumulators ----------------
__global__ void prep_kernel(){
    int i = blockIdx.x*blockDim.x + threadIdx.x;
    int stride = gridDim.x*blockDim.x;
    for (int j = i; j < NN*64; j += stride) g_agg[j] = 0.0f;
    if (i < 128){ g_bn_sum[i] = 0.0; g_bn_ssq[i] = 0.0; }
}

// ---------------- PQ[n][0:128]=x@W1, PQ[n][128:256]=x@W2 ----------------
__global__ void gemm_ab(const float* __restrict__ Wl){
    extern __shared__ float sm[];
    float* Wc = sm;             // [64][256]
    float* xt = sm + 64*256;    // [32][64]
    for (int i = threadIdx.x; i < 64*256; i += blockDim.x){
        int f = i >> 8, j = i & 255;
        Wc[i] = (j < 128) ? Wl[f*128 + j] : Wl[(64+f)*128 + (j-128)];
    }
    int n0 = blockIdx.x * 32;   // 625 * 32 == 20000 exactly
    for (int i = threadIdx.x; i < 32*64; i += blockDim.x)
        xt[i] = g_x[(n0 + (i>>6))*64 + (i&63)];
    __syncthreads();
    int j = threadIdx.x;        // 256 threads, one output column each
    float acc[32];
    #pragma unroll
    for (int t = 0; t < 32; t++) acc[t] = 0.0f;
    #pragma unroll 4
    for (int f = 0; f < 64; f++){
        float w = Wc[f*256 + j];
        #pragma unroll
        for (int t = 0; t < 32; t++) acc[t] = fmaf(xt[t*64 + f], w, acc[t]);
    }
    #pragma unroll
    for (int t = 0; t < 32; t++) g_PQ[(n0+t)*256 + j] = acc[t];
}

// ---------------- pass1: z = P[dst]+Q[src]+ef@W3+b -> Z, BN stats ----------------
__global__ void edge_pass1(const int* __restrict__ nbr, const float* __restrict__ dist,
                           const float* __restrict__ Wl, const float* __restrict__ bl){
    extern __shared__ float sm[];
    float* W3 = sm;                 // [100][128], conv_W rows 128..227
    float* bs = sm + NGAUSS*128;    // [128]
    __shared__ float s_sum[128];
    __shared__ float s_ssq[128];
    for (int i = threadIdx.x; i < NGAUSS*128; i += blockDim.x) W3[i] = Wl[128*128 + i];
    if (threadIdx.x < 128){
        bs[threadIdx.x] = bl[threadIdx.x];
        s_sum[threadIdx.x] = 0.0f; s_ssq[threadIdx.x] = 0.0f;
    }
    __syncthreads();
    int lane = threadIdx.x & 31;
    int warp = (blockIdx.x*blockDim.x + threadIdx.x) >> 5;
    int nw   = (gridDim.x*blockDim.x) >> 5;
    float4 bsv = reinterpret_cast<const float4*>(bs)[lane];
    float s0=0,s1=0,s2=0,s3=0, q0=0,q1=0,q2=0,q3=0;
    for (int e = warp; e < NE; e += nw){
        int sn = __ldg(nbr + e);        // src = neighbors_index[0]
        int dn = __ldg(nbr + NE + e);   // dst = neighbors_index[1]
        float4 p  = *reinterpret_cast<const float4*>(g_PQ + dn*256 + lane*4);
        float4 qv = *reinterpret_cast<const float4*>(g_PQ + sn*256 + 128 + lane*4);
        float z0 = p.x + qv.x + bsv.x;
        float z1 = p.y + qv.y + bsv.y;
        float z2 = p.z + qv.z + bsv.z;
        float z3 = p.w + qv.w + bsv.w;
        float d = __ldg(dist + e);
        int kc = __float2int_rn(d * INV_DELTA);
        int k0 = max(kc - GW, 0);
        int k1 = min(kc + GW, NGAUSS - 1);
        int cnt = k1 - k0 + 1;
        float myef = 0.0f;
        int mk = k0 + lane;
        if (lane < cnt){ float t = d - (float)mk*DELTA; myef = __expf(COEFF*t*t); }
        for (int k = 0; k < cnt; k++){
            float w = __shfl_sync(0xffffffffu, myef, k);
            float4 w4 = reinterpret_cast<const float4*>(W3 + (k0+k)*128)[lane];
            z0 = fmaf(w, w4.x, z0);
            z1 = fmaf(w, w4.y, z1);
            z2 = fmaf(w, w4.z, z2);
            z3 = fmaf(w, w4.w, z3);
        }
        *reinterpret_cast<float4*>(g_Z + (size_t)e*128 + lane*4) = make_float4(z0,z1,z2,z3);
        s0 += z0; s1 += z1; s2 += z2; s3 += z3;
        q0 = fmaf(z0,z0,q0); q1 = fmaf(z1,z1,q1); q2 = fmaf(z2,z2,q2); q3 = fmaf(z3,z3,q3);
    }
    int c = lane*4;
    atomicAdd(&s_sum[c+0],s0); atomicAdd(&s_sum[c+1],s1); atomicAdd(&s_sum[c+2],s2); atomicAdd(&s_sum[c+3],s3);
    atomicAdd(&s_ssq[c+0],q0); atomicAdd(&s_ssq[c+1],q1); atomicAdd(&s_ssq[c+2],q2); atomicAdd(&s_ssq[c+3],q3);
    __syncthreads();
    if (threadIdx.x < 128){
        atomicAdd(&g_bn_sum[threadIdx.x], (double)s_sum[threadIdx.x]);
        atomicAdd(&g_bn_ssq[threadIdx.x], (double)s_ssq[threadIdx.x]);
    }
}

// ---------------- BN stats -> scale/shift ----------------
__global__ void bn_finalize(const float* __restrict__ bg, const float* __restrict__ bb){
    int t = threadIdx.x;   // 128 threads
    double mu  = g_bn_sum[t] * (1.0/NE);
    double var = g_bn_ssq[t] * (1.0/NE) - mu*mu;
    double inv = 1.0 / sqrt(var + 1e-5);
    double sc  = (double)bg[t] * inv;
    g_ss[t]       = (float)sc;
    g_ss[128 + t] = (float)((double)bb[t] - mu*sc);
}

// ---------------- pass2: normalize, sigmoid*softplus, scatter to agg ----------------
__global__ void edge_pass2(const int* __restrict__ nbr){
    int lane = threadIdx.x & 31;
    float4 sc = reinterpret_cast<const float4*>(g_ss)[lane];
    float4 sh = reinterpret_cast<const float4*>(g_ss + 128)[lane];
    int warp = (blockIdx.x*blockDim.x + threadIdx.x) >> 5;
    int nw   = (gridDim.x*blockDim.x) >> 5;
    for (int e = warp; e < NE; e += nw){
        int dn = __ldg(nbr + NE + e);
        float4 z = *reinterpret_cast<const float4*>(g_Z + (size_t)e*128 + lane*4);
        float z0 = fmaf(z.x, sc.x, sh.x);
        float z1 = fmaf(z.y, sc.y, sh.y);
        float z2 = fmaf(z.z, sc.z, sh.z);
        float z3 = fmaf(z.w, sc.w, sh.w);
        float sp0 = splusf(z0), sp1 = splusf(z1), sp2 = splusf(z2), sp3 = splusf(z3);
        float o0 = __shfl_down_sync(0xffffffffu, sp0, 16);
        float o1 = __shfl_down_sync(0xffffffffu, sp1, 16);
        float o2 = __shfl_down_sync(0xffffffffu, sp2, 16);
        float o3 = __shfl_down_sync(0xffffffffu, sp3, 16);
        if (lane < 16){  // lanes 0..15 hold z1 channels 0..63; +16 holds paired z2
            float* ap = g_agg + dn*64 + lane*4;
            atomicAdd(ap+0, sigmf(z0)*o0);
            atomicAdd(ap+1, sigmf(z1)*o1);
            atomicAdd(ap+2, sigmf(z2)*o2);
            atomicAdd(ap+3, sigmf(z3)*o3);
        }
    }
}

// ---------------- LayerNorm + residual + softplus ----------------
__global__ void node_update(const float* __restrict__ lg, const float* __restrict__ lb){
    int lane = threadIdx.x & 31;
    int warp = (blockIdx.x*blockDim.x + threadIdx.x) >> 5;
    int nw   = (gridDim.x*blockDim.x) >> 5;
    float g0 = __ldg(lg + lane), g1 = __ldg(lg + lane + 32);
    float b0 = __ldg(lb + lane), b1 = __ldg(lb + lane + 32);
    for (int n = warp; n < NN; n += nw){
        float a0 = g_agg[n*64 + lane], a1 = g_agg[n*64 + lane + 32];
        float s = a0 + a1;
        #pragma unroll
        for (int o = 16; o > 0; o >>= 1) s += __shfl_xor_sync(0xffffffffu, s, o);
        float mu = s * (1.0f/64.0f);
        float d0 = a0 - mu, d1 = a1 - mu;
        float v = d0*d0 + d1*d1;
        #pragma unroll
        for (int o = 16; o > 0; o >>= 1) v += __shfl_xor_sync(0xffffffffu, v, o);
        float inv = rsqrtf(v * (1.0f/64.0f) + 1e-5f);
        float x0 = g_x[n*64 + lane], x1 = g_x[n*64 + lane + 32];
        float h0 = fmaf(d0*inv, g0, b0) + x0;
        float h1 = fmaf(d1*inv, g1, b1) + x1;
        g_x[n*64 + lane]      = splusf(h0);
        g_x[n*64 + lane + 32] = splusf(h1);
    }
}

// ---------------- mean pool per graph ----------------
__global__ void pool_prep(){
    int i = blockIdx.x*blockDim.x + threadIdx.x;
    if (i < NGR*64) g_mol[i] = 0.0f;
    if (i < NGR)    g_cnt[i] = 0.0f;
}
__global__ void pool_kernel(const int* __restrict__ batch){
    int lane = threadIdx.x & 31;
    int warp = (blockIdx.x*blockDim.x + threadIdx.x) >> 5;
    int nw   = (gridDim.x*blockDim.x) >> 5;
    for (int n = warp; n < NN; n += nw){
        int g = __ldg(batch + n);
        atomicAdd(&g_mol[g*64 + lane],      g_x[n*64 + lane]);
        atomicAdd(&g_mol[g*64 + lane + 32], g_x[n*64 + lane + 32]);
        if (lane == 0) atomicAdd(&g_cnt[g], 1.0f);
    }
}

// ---------------- MLP head ----------------
__global__ void mlp_first(const float* __restrict__ W, const float* __restrict__ b){
    __shared__ float in[64];
    int g = blockIdx.x;
    if (threadIdx.x < 64){
        float c = fmaxf(g_cnt[g], 1.0f);
        in[threadIdx.x] = g_mol[g*64 + threadIdx.x] / c;
    }
    __syncthreads();
    int j = threadIdx.x;
    float acc = b[j];
    #pragma unroll 4
    for (int f = 0; f < 64; f++) acc = fmaf(in[f], __ldg(W + f*FCW + j), acc);
    g_h1[g*FCW + j] = splusf(acc);
}
__global__ void mlp_mid(const float* __restrict__ W, const float* __restrict__ b, int sel){
    __shared__ float in[FCW];
    const float* hin = sel ? g_h2 : g_h1;
    float*      hout = sel ? g_h1 : g_h2;
    int g = blockIdx.x;
    in[threadIdx.x] = hin[g*FCW + threadIdx.x];
    __syncthreads();
    float acc = b[threadIdx.x];
    #pragma unroll 4
    for (int f = 0; f < FCW; f++) acc = fmaf(in[f], __ldg(W + f*FCW + threadIdx.x), acc);
    hout[g*FCW + threadIdx.x] = splusf(acc);
}
__global__ void mlp_out(const float* __restrict__ W, const float* __restrict__ b,
                        float* __restrict__ out, int sel){
    __shared__ float red[FCW];
    const float* hin = sel ? g_h2 : g_h1;
    int g = blockIdx.x;
    red[threadIdx.x] = hin[g*FCW + threadIdx.x] * __ldg(W + threadIdx.x);
    __syncthreads();
    for (int o = 64; o > 0; o >>= 1){
        if (threadIdx.x < o) red[threadIdx.x] += red[threadIdx.x + o];
        __syncthreads();
    }
    if (threadIdx.x == 0) out[g] = red[0] + b[0];
}

// ---------------- launch ----------------
extern "C" void kernel_launch(void* const* d_in, const int* in_sizes, int n_in,
                              void* d_out, int out_size){
    const int*   an    = (const int*)  d_in[0];
    const int*   nbr   = (const int*)  d_in[1];
    const float* dist  = (const float*)d_in[2];
    const int*   batch = (const int*)  d_in[3];
    const float* emb   = (const float*)d_in[4];
    const float* nucW  = (const float*)d_in[5];
    const float* nucb  = (const float*)d_in[6];
    const float* convW = (const float*)d_in[7];
    const float* convb = (const float*)d_in[8];
    const float* bng   = (const float*)d_in[9];
    const float* bnb   = (const float*)d_in[10];
    const float* lng   = (const float*)d_in[11];
    const float* lnb   = (const float*)d_in[12];
    const float* fc1W  = (const float*)d_in[13];
    const float* fc1b  = (const float*)d_in[14];
    const float* fcsW  = (const float*)d_in[15];
    const float* fcsb  = (const float*)d_in[16];
    const float* outW  = (const float*)d_in[17];
    const float* outb  = (const float*)d_in[18];
    float* y = (float*)d_out;

    cudaFuncSetAttribute(gemm_ab,    cudaFuncAttributeMaxDynamicSharedMemorySize, GEMM_SMEM);
    cudaFuncSetAttribute(edge_pass1, cudaFuncAttributeMaxDynamicSharedMemorySize, P1_SMEM);

    nuc_kernel<<<640, 256>>>(an, emb, nucW, nucb);
    for (int l = 0; l < NLAYER; l++){
        prep_kernel<<<640, 256>>>();
        gemm_ab<<<625, 256, GEMM_SMEM>>>(convW + l*228*128);
        edge_pass1<<<592, 256, P1_SMEM>>>(nbr, dist, convW + l*228*128, convb + l*128);
        bn_finalize<<<1, 128>>>(bng + l*128, bnb + l*128);
        edge_pass2<<<1480, 256>>>(nbr);
        node_update<<<640, 256>>>(lng + l*64, lnb + l*64);
    }
    pool_prep<<<17, 256>>>();
    pool_kernel<<<640, 256>>>(batch);
    mlp_first<<<NGR, FCW>>>(fc1W, fc1b);
    mlp_mid<<<NGR, FCW>>>(fcsW,             fcsb,         0);
    mlp_mid<<<NGR, FCW>>>(fcsW + FCW*FCW,   fcsb + FCW,   1);
    mlp_mid<<<NGR, FCW>>>(fcsW + 2*FCW*FCW, fcsb + 2*FCW, 0);
    mlp_out<<<NGR, FCW>>>(outW, outb, y, 1);
}

// round 6
// speedup vs baseline: 1.2413x; 1.2413x over previous
#include <cuda_runtime.h>
#include <math.h>

#define NN      20000
#define NE      500000
#define NGR     64
#define NGAUSS  100
#define NLAYER  6
#define FCW     128
#define EMBW    92

#define DELTA     (6.0f/99.0f)
#define INV_DELTA (99.0f/6.0f)
#define COEFF     (-0.5f/(DELTA*DELTA))

// interp table: h = DELTA/64
#define MTAB      6338
#define TAB_H     (6.0f/6336.0f)
#define TAB_INVH  (6336.0f/6.0f)

#define GEMM_SMEM ((64*256 + 32*64)*4)

// ---------------- scratch (device globals; no allocs allowed) ----------------
__device__ float  g_x[NN*64];
__device__ float  g_PQ[NN*256];
__device__ float  g_Z[NE*128];          // edge pre-activation scratch (CSR order)
__device__ float  g_T[MTAB*128];        // ef@W3 + b interp table
__device__ int    g_deg[NN];
__device__ int    g_rowstart[NN+1];
__device__ int    g_cursor[NN];
__device__ int    g_srcs[NE];           // src node per CSR slot
__device__ float  g_dists[NE];          // distance per CSR slot
__device__ double g_bn_sum[128];
__device__ double g_bn_ssq[128];
__device__ float  g_ss[256];            // BN scale[128] | shift[128]
__device__ float  g_mol[NGR*64];
__device__ float  g_cnt[NGR];
__device__ float  g_h1[NGR*FCW];
__device__ float  g_h2[NGR*FCW];

// ---------------- helpers ----------------
__device__ __forceinline__ float splusf(float x){
    float e = __expf(-fabsf(x));
    return fmaxf(x, 0.0f) + __logf(1.0f + e);
}
__device__ __forceinline__ float sigmf(float x){
    float e = __expf(-fabsf(x));
    float r = __fdividef(1.0f, 1.0f + e);
    return (x >= 0.0f) ? r : e * r;
}

// ---------------- x = embedding[an] @ nuc_W + nuc_b ----------------
__global__ void nuc_kernel(const int* __restrict__ an, const float* __restrict__ emb,
                           const float* __restrict__ W, const float* __restrict__ b){
    __shared__ float Ws[EMBW*64];
    __shared__ float bs[64];
    for (int i = threadIdx.x; i < EMBW*64; i += blockDim.x) Ws[i] = W[i];
    if (threadIdx.x < 64) bs[threadIdx.x] = b[threadIdx.x];
    __syncthreads();
    int lane = threadIdx.x & 31;
    int warp = (blockIdx.x*blockDim.x + threadIdx.x) >> 5;
    int nw   = (gridDim.x*blockDim.x) >> 5;
    for (int n = warp; n < NN; n += nw){
        const float* er = emb + an[n]*EMBW;
        float a0 = bs[lane], a1 = bs[lane+32];
        #pragma unroll 4
        for (int e = 0; e < EMBW; e++){
            float v = __ldg(er + e);
            a0 = fmaf(v, Ws[e*64 + lane],      a0);
            a1 = fmaf(v, Ws[e*64 + lane + 32], a1);
        }
        g_x[n*64 + lane]      = a0;
        g_x[n*64 + lane + 32] = a1;
    }
}

// ---------------- CSR build (once per launch) ----------------
__global__ void csr_zero(){
    int i = blockIdx.x*blockDim.x + threadIdx.x;
    if (i < NN) g_deg[i] = 0;
}
__global__ void csr_hist(const int* __restrict__ nbr){
    int i = blockIdx.x*blockDim.x + threadIdx.x;
    int stride = gridDim.x*blockDim.x;
    for (int e = i; e < NE; e += stride)
        atomicAdd(&g_deg[__ldg(nbr + NE + e)], 1);
}
__global__ void csr_scan(){   // single block, 1024 threads; 1000*20 = 20000
    __shared__ int s[1024];
    int t = threadIdx.x;
    int base = t*20;
    int loc = 0;
    if (base < NN)
        for (int j = 0; j < 20; j++) loc += g_deg[base + j];
    s[t] = loc;
    __syncthreads();
    for (int off = 1; off < 1024; off <<= 1){
        int v = (t >= off) ? s[t - off] : 0;
        __syncthreads();
        s[t] += v;
        __syncthreads();
    }
    if (base < NN){
        int run = s[t] - loc;
        for (int j = 0; j < 20; j++){
            g_rowstart[base + j] = run;
            g_cursor[base + j]   = run;
            run += g_deg[base + j];
        }
    }
    if (t == 1023) g_rowstart[NN] = s[1023];
}
__global__ void csr_scatter(const int* __restrict__ nbr, const float* __restrict__ dist){
    int i = blockIdx.x*blockDim.x + threadIdx.x;
    int stride = gridDim.x*blockDim.x;
    for (int e = i; e < NE; e += stride){
        int dn = __ldg(nbr + NE + e);
        int pos = atomicAdd(&g_cursor[dn], 1);
        g_srcs[pos]  = __ldg(nbr + e);
        g_dists[pos] = __ldg(dist + e);
    }
}

// ---------------- per-layer: zero BN accumulators ----------------
__global__ void bn_zero(){
    int i = threadIdx.x;
    g_bn_sum[i] = 0.0; g_bn_ssq[i] = 0.0;
}

// ---------------- PQ[n][0:128]=x@W1(dst), PQ[n][128:256]=x@W2(src) ----------------
__global__ void gemm_ab(const float* __restrict__ Wl){
    extern __shared__ float sm[];
    float* Wc = sm;             // [64][256]
    float* xt = sm + 64*256;    // [32][64]
    for (int i = threadIdx.x; i < 64*256; i += blockDim.x){
        int f = i >> 8, j = i & 255;
        Wc[i] = (j < 128) ? Wl[f*128 + j] : Wl[(64+f)*128 + (j-128)];
    }
    int n0 = blockIdx.x * 32;   // 625 * 32 == 20000
    for (int i = threadIdx.x; i < 32*64; i += blockDim.x)
        xt[i] = g_x[(n0 + (i>>6))*64 + (i&63)];
    __syncthreads();
    int j = threadIdx.x;
    float acc[32];
    #pragma unroll
    for (int t = 0; t < 32; t++) acc[t] = 0.0f;
    #pragma unroll 4
    for (int f = 0; f < 64; f++){
        float w = Wc[f*256 + j];
        #pragma unroll
        for (int t = 0; t < 32; t++) acc[t] = fmaf(xt[t*64 + f], w, acc[t]);
    }
    #pragma unroll
    for (int t = 0; t < 32; t++) g_PQ[(n0+t)*256 + j] = acc[t];
}

// ---------------- build T[m] = ef(m*h)@W3 + conv_b ----------------
__global__ void build_table(const float* __restrict__ Wl, const float* __restrict__ bl){
    int m = blockIdx.x;            // MTAB blocks
    int j = threadIdx.x;           // 128 threads
    float d = (float)m * TAB_H;
    int kc = __float2int_rn(d * INV_DELTA);
    int k0 = max(kc - 8, 0);
    int k1 = min(kc + 8, NGAUSS - 1);
    float acc = __ldg(bl + j);
    const float* W3 = Wl + 128*128;
    for (int k = k0; k <= k1; k++){
        float t = d - (float)k * DELTA;
        acc = fmaf(__expf(COEFF*t*t), __ldg(W3 + k*128 + j), acc);
    }
    g_T[m*128 + j] = acc;
}

// ---------------- pass1 (warp per node): z -> Z (CSR order), BN stats ----------------
__global__ void edge_pass1(){
    __shared__ float s_sum[128];
    __shared__ float s_ssq[128];
    if (threadIdx.x < 128){ s_sum[threadIdx.x] = 0.0f; s_ssq[threadIdx.x] = 0.0f; }
    __syncthreads();
    int lane = threadIdx.x & 31;
    int warp = (blockIdx.x*blockDim.x + threadIdx.x) >> 5;
    int nw   = (gridDim.x*blockDim.x) >> 5;
    float s0=0,s1=0,s2=0,s3=0, q0=0,q1=0,q2=0,q3=0;
    for (int n = warp; n < NN; n += nw){
        int i0 = g_rowstart[n], i1 = g_rowstart[n+1];
        float4 p = *reinterpret_cast<const float4*>(g_PQ + n*256 + lane*4);
        for (int i = i0; i < i1; i++){
            int sn = __ldg(&g_srcs[i]);
            float d = __ldg(&g_dists[i]);
            float4 qv = *reinterpret_cast<const float4*>(g_PQ + sn*256 + 128 + lane*4);
            float fm = d * TAB_INVH;
            int   m  = min((int)fm, MTAB - 2);
            float fr = fm - (float)m;
            float4 t0 = *reinterpret_cast<const float4*>(g_T + m*128 + lane*4);
            float4 t1 = *reinterpret_cast<const float4*>(g_T + (m+1)*128 + lane*4);
            float z0 = p.x + qv.x + fmaf(fr, t1.x - t0.x, t0.x);
            float z1 = p.y + qv.y + fmaf(fr, t1.y - t0.y, t0.y);
            float z2 = p.z + qv.z + fmaf(fr, t1.z - t0.z, t0.z);
            float z3 = p.w + qv.w + fmaf(fr, t1.w - t0.w, t0.w);
            *reinterpret_cast<float4*>(g_Z + (size_t)i*128 + lane*4) = make_float4(z0,z1,z2,z3);
            s0 += z0; s1 += z1; s2 += z2; s3 += z3;
            q0 = fmaf(z0,z0,q0); q1 = fmaf(z1,z1,q1); q2 = fmaf(z2,z2,q2); q3 = fmaf(z3,z3,q3);
        }
    }
    int c = lane*4;
    atomicAdd(&s_sum[c+0],s0); atomicAdd(&s_sum[c+1],s1); atomicAdd(&s_sum[c+2],s2); atomicAdd(&s_sum[c+3],s3);
    atomicAdd(&s_ssq[c+0],q0); atomicAdd(&s_ssq[c+1],q1); atomicAdd(&s_ssq[c+2],q2); atomicAdd(&s_ssq[c+3],q3);
    __syncthreads();
    if (threadIdx.x < 128){
        atomicAdd(&g_bn_sum[threadIdx.x], (double)s_sum[threadIdx.x]);
        atomicAdd(&g_bn_ssq[threadIdx.x], (double)s_ssq[threadIdx.x]);
    }
}

// ---------------- BN stats -> scale/shift ----------------
__global__ void bn_finalize(const float* __restrict__ bg, const float* __restrict__ bb){
    int t = threadIdx.x;   // 128
    double mu  = g_bn_sum[t] * (1.0/NE);
    double var = g_bn_ssq[t] * (1.0/NE) - mu*mu;
    double inv = 1.0 / sqrt(var + 1e-5);
    double sc  = (double)bg[t] * inv;
    g_ss[t]       = (float)sc;
    g_ss[128 + t] = (float)((double)bb[t] - mu*sc);
}

// ---- pass2 (warp per node): BN affine + sig*softplus + agg + LN + residual ----
__global__ void edge_pass2(const float* __restrict__ lng, const float* __restrict__ lnb){
    int lane = threadIdx.x & 31;
    int warp = (blockIdx.x*blockDim.x + threadIdx.x) >> 5;
    int nw   = (gridDim.x*blockDim.x) >> 5;
    float4 sc = reinterpret_cast<const float4*>(g_ss)[lane];
    float4 sh = reinterpret_cast<const float4*>(g_ss + 128)[lane];
    int cl = min(lane, 15);
    float4 lg = *reinterpret_cast<const float4*>(lng + cl*4);
    float4 lb = *reinterpret_cast<const float4*>(lnb + cl*4);
    for (int n = warp; n < NN; n += nw){
        int i0 = g_rowstart[n], i1 = g_rowstart[n+1];
        float a0=0,a1=0,a2=0,a3=0;
        for (int i = i0; i < i1; i++){
            float4 z = *reinterpret_cast<const float4*>(g_Z + (size_t)i*128 + lane*4);
            float z0 = fmaf(z.x, sc.x, sh.x);
            float z1 = fmaf(z.y, sc.y, sh.y);
            float z2 = fmaf(z.z, sc.z, sh.z);
            float z3 = fmaf(z.w, sc.w, sh.w);
            float sp0 = splusf(z0), sp1 = splusf(z1), sp2 = splusf(z2), sp3 = splusf(z3);
            float o0 = __shfl_down_sync(0xffffffffu, sp0, 16);
            float o1 = __shfl_down_sync(0xffffffffu, sp1, 16);
            float o2 = __shfl_down_sync(0xffffffffu, sp2, 16);
            float o3 = __shfl_down_sync(0xffffffffu, sp3, 16);
            if (lane < 16){
                a0 = fmaf(sigmf(z0), o0, a0);
                a1 = fmaf(sigmf(z1), o1, a1);
                a2 = fmaf(sigmf(z2), o2, a2);
                a3 = fmaf(sigmf(z3), o3, a3);
            }
        }
        // LayerNorm over 64 channels (held by lanes 0..15, 4 each)
        float s = a0 + a1 + a2 + a3;
        #pragma unroll
        for (int o = 8; o > 0; o >>= 1) s += __shfl_xor_sync(0xffffffffu, s, o);
        float mu = s * (1.0f/64.0f);
        float d0 = a0 - mu, d1 = a1 - mu, d2 = a2 - mu, d3 = a3 - mu;
        float v = d0*d0 + d1*d1 + d2*d2 + d3*d3;
        #pragma unroll
        for (int o = 8; o > 0; o >>= 1) v += __shfl_xor_sync(0xffffffffu, v, o);
        float inv = rsqrtf(v * (1.0f/64.0f) + 1e-5f);
        if (lane < 16){
            float4 x = *reinterpret_cast<const float4*>(g_x + n*64 + lane*4);
            float h0 = fmaf(d0*inv, lg.x, lb.x) + x.x;
            float h1 = fmaf(d1*inv, lg.y, lb.y) + x.y;
            float h2 = fmaf(d2*inv, lg.z, lb.z) + x.z;
            float h3 = fmaf(d3*inv, lg.w, lb.w) + x.w;
            *reinterpret_cast<float4*>(g_x + n*64 + lane*4) =
                make_float4(splusf(h0), splusf(h1), splusf(h2), splusf(h3));
        }
    }
}

// ---------------- mean pool per graph ----------------
__global__ void pool_prep(){
    int i = blockIdx.x*blockDim.x + threadIdx.x;
    if (i < NGR*64) g_mol[i] = 0.0f;
    if (i < NGR)    g_cnt[i] = 0.0f;
}
__global__ void pool_kernel(const int* __restrict__ batch){
    int lane = threadIdx.x & 31;
    int warp = (blockIdx.x*blockDim.x + threadIdx.x) >> 5;
    int nw   = (gridDim.x*blockDim.x) >> 5;
    for (int n = warp; n < NN; n += nw){
        int g = __ldg(batch + n);
        atomicAdd(&g_mol[g*64 + lane],      g_x[n*64 + lane]);
        atomicAdd(&g_mol[g*64 + lane + 32], g_x[n*64 + lane + 32]);
        if (lane == 0) atomicAdd(&g_cnt[g], 1.0f);
    }
}

// ---------------- MLP head ----------------
__global__ void mlp_first(const float* __restrict__ W, const float* __restrict__ b){
    __shared__ float in[64];
    int g = blockIdx.x;
    if (threadIdx.x < 64){
        float c = fmaxf(g_cnt[g], 1.0f);
        in[threadIdx.x] = g_mol[g*64 + threadIdx.x] / c;
    }
    __syncthreads();
    int j = threadIdx.x;
    float acc = b[j];
    #pragma unroll 4
    for (int f = 0; f < 64; f++) acc = fmaf(in[f], __ldg(W + f*FCW + j), acc);
    g_h1[g*FCW + j] = splusf(acc);
}
__global__ void mlp_mid(const float* __restrict__ W, const float* __restrict__ b, int sel){
    __shared__ float in[FCW];
    const float* hin = sel ? g_h2 : g_h1;
    float*      hout = sel ? g_h1 : g_h2;
    int g = blockIdx.x;
    in[threadIdx.x] = hin[g*FCW + threadIdx.x];
    __syncthreads();
    float acc = b[threadIdx.x];
    #pragma unroll 4
    for (int f = 0; f < FCW; f++) acc = fmaf(in[f], __ldg(W + f*FCW + threadIdx.x), acc);
    hout[g*FCW + threadIdx.x] = splusf(acc);
}
__global__ void mlp_out(const float* __restrict__ W, const float* __restrict__ b,
                        float* __restrict__ out, int sel){
    __shared__ float red[FCW];
    const float* hin = sel ? g_h2 : g_h1;
    int g = blockIdx.x;
    red[threadIdx.x] = hin[g*FCW + threadIdx.x] * __ldg(W + threadIdx.x);
    __syncthreads();
    for (int o = 64; o > 0; o >>= 1){
        if (threadIdx.x < o) red[threadIdx.x] += red[threadIdx.x + o];
        __syncthreads();
    }
    if (threadIdx.x == 0) out[g] = red[0] + b[0];
}

// ---------------- launch ----------------
extern "C" void kernel_launch(void* const* d_in, const int* in_sizes, int n_in,
                              void* d_out, int out_size){
    const int*   an    = (const int*)  d_in[0];
    const int*   nbr   = (const int*)  d_in[1];
    const float* dist  = (const float*)d_in[2];
    const int*   batch = (const int*)  d_in[3];
    const float* emb   = (const float*)d_in[4];
    const float* nucW  = (const float*)d_in[5];
    const float* nucb  = (const float*)d_in[6];
    const float* convW = (const float*)d_in[7];
    const float* convb = (const float*)d_in[8];
    const float* bng   = (const float*)d_in[9];
    const float* bnb   = (const float*)d_in[10];
    const float* lng   = (const float*)d_in[11];
    const float* lnb   = (const float*)d_in[12];
    const float* fc1W  = (const float*)d_in[13];
    const float* fc1b  = (const float*)d_in[14];
    const float* fcsW  = (const float*)d_in[15];
    const float* fcsb  = (const float*)d_in[16];
    const float* outW  = (const float*)d_in[17];
    const float* outb  = (const float*)d_in[18];
    float* y = (float*)d_out;

    cudaFuncSetAttribute(gemm_ab, cudaFuncAttributeMaxDynamicSharedMemorySize, GEMM_SMEM);

    // CSR build (amortized over layers) + initial embedding
    csr_zero<<<79, 256>>>();
    nuc_kernel<<<640, 256>>>(an, emb, nucW, nucb);
    csr_hist<<<640, 256>>>(nbr);
    csr_scan<<<1, 1024>>>();
    csr_scatter<<<640, 256>>>(nbr, dist);

    for (int l = 0; l < NLAYER; l++){
        bn_zero<<<1, 128>>>();
        gemm_ab<<<625, 256, GEMM_SMEM>>>(convW + l*228*128);
        build_table<<<MTAB, 128>>>(convW + l*228*128, convb + l*128);
        edge_pass1<<<640, 256>>>();
        bn_finalize<<<1, 128>>>(bng + l*128, bnb + l*128);
        edge_pass2<<<640, 256>>>(lng + l*64, lnb + l*64);
    }
    pool_prep<<<17, 256>>>();
    pool_kernel<<<640, 256>>>(batch);
    mlp_first<<<NGR, FCW>>>(fc1W, fc1b);
    mlp_mid<<<NGR, FCW>>>(fcsW,             fcsb,         0);
    mlp_mid<<<NGR, FCW>>>(fcsW + FCW*FCW,   fcsb + FCW,   1);
    mlp_mid<<<NGR, FCW>>>(fcsW + 2*FCW*FCW, fcsb + 2*FCW, 0);
    mlp_out<<<NGR, FCW>>>(outW, outb, y, 1);
}

// round 7
// speedup vs baseline: 2.1850x; 1.7602x over previous
#include <cuda_runtime.h>
#include <cuda_fp16.h>
#include <math.h>

#define NN      20000
#define NNP     20480        // padded for csr_scan vector path
#define NE      500000
#define NGR     64
#define NGAUSS  100
#define NLAYER  6
#define FCW     128
#define EMBW    92

#define DELTA     (6.0f/99.0f)
#define INV_DELTA (99.0f/6.0f)
#define COEFF     (-0.5f/(DELTA*DELTA))

// nearest-neighbor table: h = DELTA/256
#define MT2       25346
#define T2_INVH   4224.0f    // 99*256/6
#define T2_H      (1.0f/4224.0f)

#define GEMM_SMEM  ((64*256 + 32*64)*4)
#define TAB_SMEM   ((NGAUSS*128 + 128 + 32)*4)

// ---------------- scratch (device globals; no allocs allowed) ----------------
__device__ float  g_x[NN*64];
__device__ __half g_PQh[NN*256];        // permuted: P[0:128] | Q[128:256], fp16
__device__ __half g_Th[MT2*128];        // ef@W3 + b table, permuted, fp16
__device__ int    g_deg[NNP];
__device__ int    g_rowstart[NNP+1];
__device__ int    g_cursor[NNP];
__device__ unsigned int g_pack[NE];     // src (15b) | m (<<15)
__device__ double g_bn_sum[128];
__device__ double g_bn_ssq[128];
__device__ float  g_ss[256];            // BN scale[128] | shift[128] (pos-space)
__device__ float  g_mol[NGR*64];
__device__ float  g_cnt[NGR];

// ---------------- helpers ----------------
__device__ __forceinline__ float splusf(float x){
    float e = __expf(-fabsf(x));
    return fmaxf(x, 0.0f) + __logf(1.0f + e);
}
__device__ __forceinline__ float sigmf(float x){
    float e = __expf(-fabsf(x));
    float r = __fdividef(1.0f, 1.0f + e);
    return (x >= 0.0f) ? r : e * r;
}
// channel c (0..127) -> permuted position: lane L holds {2L,2L+1,2L+64,2L+65}
__device__ __forceinline__ int chpos(int c){
    return ((c & 63) >> 1)*4 + ((c >> 6) << 1) + (c & 1);
}
__device__ __forceinline__ void ld_h4(const __half* p, float& a, float& b, float& c, float& d){
    uint2 u = *reinterpret_cast<const uint2*>(p);
    float2 f0 = __half22float2(*reinterpret_cast<__half2*>(&u.x));
    float2 f1 = __half22float2(*reinterpret_cast<__half2*>(&u.y));
    a = f0.x; b = f0.y; c = f1.x; d = f1.y;
}

// ---------------- x = embedding[an] @ nuc_W + nuc_b ----------------
__global__ void nuc_kernel(const int* __restrict__ an, const float* __restrict__ emb,
                           const float* __restrict__ W, const float* __restrict__ b){
    __shared__ float Ws[EMBW*64];
    __shared__ float bs[64];
    for (int i = threadIdx.x; i < EMBW*64; i += blockDim.x) Ws[i] = W[i];
    if (threadIdx.x < 64) bs[threadIdx.x] = b[threadIdx.x];
    __syncthreads();
    int lane = threadIdx.x & 31;
    int warp = (blockIdx.x*blockDim.x + threadIdx.x) >> 5;
    int nw   = (gridDim.x*blockDim.x) >> 5;
    for (int n = warp; n < NN; n += nw){
        const float* er = emb + an[n]*EMBW;
        float a0 = bs[lane], a1 = bs[lane+32];
        #pragma unroll 4
        for (int e = 0; e < EMBW; e++){
            float v = __ldg(er + e);
            a0 = fmaf(v, Ws[e*64 + lane],      a0);
            a1 = fmaf(v, Ws[e*64 + lane + 32], a1);
        }
        g_x[n*64 + lane]      = a0;
        g_x[n*64 + lane + 32] = a1;
    }
}

// ---------------- CSR build (once per launch) ----------------
__global__ void csr_zero(){
    int i = blockIdx.x*blockDim.x + threadIdx.x;
    if (i < NNP) g_deg[i] = 0;
}
__global__ void csr_hist(const int* __restrict__ nbr){
    int i = blockIdx.x*blockDim.x + threadIdx.x;
    int stride = gridDim.x*blockDim.x;
    for (int e = i; e < NE; e += stride)
        atomicAdd(&g_deg[__ldg(nbr + NE + e)], 1);
}
__global__ void csr_scan(){   // single block, 1024 threads, 20 items each (padded)
    __shared__ int s[1024];
    int t = threadIdx.x;
    int base = t*20;
    int4 v[5];
    int loc = 0;
    #pragma unroll
    for (int j = 0; j < 5; j++){
        v[j] = *reinterpret_cast<const int4*>(g_deg + base + j*4);
        loc += v[j].x + v[j].y + v[j].z + v[j].w;
    }
    s[t] = loc;
    __syncthreads();
    for (int off = 1; off < 1024; off <<= 1){
        int u = (t >= off) ? s[t - off] : 0;
        __syncthreads();
        s[t] += u;
        __syncthreads();
    }
    int run = s[t] - loc;
    #pragma unroll
    for (int j = 0; j < 5; j++){
        int4 rs;
        rs.x = run; run += v[j].x;
        rs.y = run; run += v[j].y;
        rs.z = run; run += v[j].z;
        rs.w = run; run += v[j].w;
        *reinterpret_cast<int4*>(g_rowstart + base + j*4) = rs;
        *reinterpret_cast<int4*>(g_cursor   + base + j*4) = rs;
    }
    if (t == 1023) g_rowstart[NNP] = s[1023];  // == NE; rowstart[NN] set by padded writes
}
__global__ void csr_scatter(const int* __restrict__ nbr, const float* __restrict__ dist){
    int i = blockIdx.x*blockDim.x + threadIdx.x;
    int stride = gridDim.x*blockDim.x;
    for (int e = i; e < NE; e += stride){
        int dn = __ldg(nbr + NE + e);
        int sn = __ldg(nbr + e);
        float d = __ldg(dist + e);
        int m = min(__float2int_rn(d * T2_INVH), MT2 - 1);
        int pos = atomicAdd(&g_cursor[dn], 1);
        g_pack[pos] = (unsigned)sn | ((unsigned)m << 15);
    }
}

// ---------------- PQ = x@[W1|W2] (fp16, permuted) ----------------
__global__ void gemm_ab(const float* __restrict__ Wl){
    extern __shared__ float sm[];
    float* Wc = sm;             // [64][256]
    float* xt = sm + 64*256;    // [32][64]
    for (int i = threadIdx.x; i < 64*256; i += blockDim.x){
        int f = i >> 8, j = i & 255;
        Wc[i] = (j < 128) ? Wl[f*128 + j] : Wl[(64+f)*128 + (j-128)];
    }
    int n0 = blockIdx.x * 32;   // 625 * 32 == 20000
    for (int i = threadIdx.x; i < 32*64; i += blockDim.x)
        xt[i] = g_x[(n0 + (i>>6))*64 + (i&63)];
    __syncthreads();
    int j = threadIdx.x;
    float acc[32];
    #pragma unroll
    for (int t = 0; t < 32; t++) acc[t] = 0.0f;
    for (int f = 0; f < 64; f += 4){
        float w0 = Wc[f*256 + j], w1 = Wc[(f+1)*256 + j];
        float w2 = Wc[(f+2)*256 + j], w3 = Wc[(f+3)*256 + j];
        #pragma unroll
        for (int t = 0; t < 32; t++){
            float4 xv = *reinterpret_cast<const float4*>(xt + t*64 + f);
            acc[t] = fmaf(xv.x, w0, fmaf(xv.y, w1, fmaf(xv.z, w2, fmaf(xv.w, w3, acc[t]))));
        }
    }
    int part = j >> 7;                 // 0 = P, 1 = Q
    int off  = part*128 + chpos(j & 127);
    #pragma unroll
    for (int t = 0; t < 32; t++)
        g_PQh[(n0+t)*256 + off] = __float2half_rn(acc[t]);
}

// ---------------- build T[m] = ef(m*h)@W3 + conv_b (fp16, permuted) ----------------
// also zeroes BN accumulators (block 0)
__global__ void build_table(const float* __restrict__ Wl, const float* __restrict__ bl){
    extern __shared__ float sm[];
    float* W3s = sm;                 // [100][128]
    float* bs  = sm + NGAUSS*128;    // [128]
    float* wsm = bs + 128;           // [<=20]
    const float* W3 = Wl + 128*128;
    for (int i = threadIdx.x; i < NGAUSS*128; i += blockDim.x) W3s[i] = W3[i];
    if (threadIdx.x < 128) bs[threadIdx.x] = bl[threadIdx.x];
    if (blockIdx.x == 0 && threadIdx.x < 128){
        g_bn_sum[threadIdx.x] = 0.0; g_bn_ssq[threadIdx.x] = 0.0;
    }
    __syncthreads();
    int j  = threadIdx.x;            // 128 threads
    int pj = chpos(j);
    int per = (MT2 + gridDim.x - 1) / gridDim.x;
    int m0 = blockIdx.x*per;
    int m1 = min(m0 + per, MT2);
    for (int m = m0; m < m1; m++){
        float d = (float)m * T2_H;
        int kc = __float2int_rn(d * INV_DELTA);
        int k0 = max(kc - 8, 0);
        int k1 = min(kc + 8, NGAUSS - 1);
        int cnt = k1 - k0 + 1;
        if (j < cnt){ float t = d - (float)(k0+j)*DELTA; wsm[j] = __expf(COEFF*t*t); }
        __syncthreads();
        float acc = bs[j];
        for (int k = 0; k < cnt; k++) acc = fmaf(wsm[k], W3s[(k0+k)*128 + j], acc);
        g_Th[m*128 + pj] = __float2half_rn(acc);
        __syncthreads();
    }
}

// ---------------- pass1 (warp per node): BN stats only, no Z store ----------------
__global__ void edge_pass1(){
    __shared__ float s_sum[128];
    __shared__ float s_ssq[128];
    if (threadIdx.x < 128){ s_sum[threadIdx.x] = 0.0f; s_ssq[threadIdx.x] = 0.0f; }
    __syncthreads();
    int lane = threadIdx.x & 31;
    int warp = (blockIdx.x*blockDim.x + threadIdx.x) >> 5;
    int nw   = (gridDim.x*blockDim.x) >> 5;
    float s0=0,s1=0,s2=0,s3=0, q0=0,q1=0,q2=0,q3=0;
    for (int n = warp; n < NN; n += nw){
        int i0 = g_rowstart[n], i1 = g_rowstart[n+1];
        float p0,p1,p2,p3;
        ld_h4(g_PQh + n*256 + lane*4, p0,p1,p2,p3);
        for (int i = i0; i < i1; i++){
            unsigned v = __ldg(&g_pack[i]);
            int sn = v & 0x7FFF;
            int m  = v >> 15;
            float a0,a1,a2,a3, t0,t1,t2,t3;
            ld_h4(g_PQh + sn*256 + 128 + lane*4, a0,a1,a2,a3);
            ld_h4(g_Th + m*128 + lane*4, t0,t1,t2,t3);
            float z0 = p0 + a0 + t0;
            float z1 = p1 + a1 + t1;
            float z2 = p2 + a2 + t2;
            float z3 = p3 + a3 + t3;
            s0 += z0; s1 += z1; s2 += z2; s3 += z3;
            q0 = fmaf(z0,z0,q0); q1 = fmaf(z1,z1,q1);
            q2 = fmaf(z2,z2,q2); q3 = fmaf(z3,z3,q3);
        }
    }
    int c = lane*4;   // pos-space
    atomicAdd(&s_sum[c+0],s0); atomicAdd(&s_sum[c+1],s1); atomicAdd(&s_sum[c+2],s2); atomicAdd(&s_sum[c+3],s3);
    atomicAdd(&s_ssq[c+0],q0); atomicAdd(&s_ssq[c+1],q1); atomicAdd(&s_ssq[c+2],q2); atomicAdd(&s_ssq[c+3],q3);
    __syncthreads();
    if (threadIdx.x < 128){
        atomicAdd(&g_bn_sum[threadIdx.x], (double)s_sum[threadIdx.x]);
        atomicAdd(&g_bn_ssq[threadIdx.x], (double)s_ssq[threadIdx.x]);
    }
}

// ---------------- BN stats -> scale/shift (pos-space) ----------------
__global__ void bn_finalize(const float* __restrict__ bg, const float* __restrict__ bb){
    int t = threadIdx.x;   // 128 (pos index)
    int c = 2*(t >> 2) + (t & 1) + (((t >> 1) & 1) << 6);   // inverse perm
    double mu  = g_bn_sum[t] * (1.0/NE);
    double var = g_bn_ssq[t] * (1.0/NE) - mu*mu;
    double inv = 1.0 / sqrt(var + 1e-5);
    double sc  = (double)bg[c] * inv;
    g_ss[t]       = (float)sc;
    g_ss[128 + t] = (float)((double)bb[c] - mu*sc);
}

// ---- pass2 (warp per node): recompute z, BN affine, sig*softplus, agg, LN, residual ----
__global__ void edge_pass2(const float* __restrict__ lng, const float* __restrict__ lnb){
    int lane = threadIdx.x & 31;
    int warp = (blockIdx.x*blockDim.x + threadIdx.x) >> 5;
    int nw   = (gridDim.x*blockDim.x) >> 5;
    float4 sc = *reinterpret_cast<const float4*>(g_ss + lane*4);
    float4 sh = *reinterpret_cast<const float4*>(g_ss + 128 + lane*4);
    float2 lg = *reinterpret_cast<const float2*>(lng + 2*lane);
    float2 lb = *reinterpret_cast<const float2*>(lnb + 2*lane);
    for (int n = warp; n < NN; n += nw){
        int i0 = g_rowstart[n], i1 = g_rowstart[n+1];
        float p0,p1,p2,p3;
        ld_h4(g_PQh + n*256 + lane*4, p0,p1,p2,p3);
        float a0 = 0.0f, a1 = 0.0f;
        for (int i = i0; i < i1; i++){
            unsigned v = __ldg(&g_pack[i]);
            int sn = v & 0x7FFF;
            int m  = v >> 15;
            float b0,b1,b2,b3, t0,t1,t2,t3;
            ld_h4(g_PQh + sn*256 + 128 + lane*4, b0,b1,b2,b3);
            ld_h4(g_Th + m*128 + lane*4, t0,t1,t2,t3);
            float z0 = fmaf(p0 + b0 + t0, sc.x, sh.x);
            float z1 = fmaf(p1 + b1 + t1, sc.y, sh.y);
            float z2 = fmaf(p2 + b2 + t2, sc.z, sh.z);
            float z3 = fmaf(p3 + b3 + t3, sc.w, sh.w);
            a0 = fmaf(sigmf(z0), splusf(z2), a0);   // channel 2L
            a1 = fmaf(sigmf(z1), splusf(z3), a1);   // channel 2L+1
        }
        // LayerNorm over 64 channels (2 per lane)
        float s = a0 + a1;
        #pragma unroll
        for (int o = 16; o > 0; o >>= 1) s += __shfl_xor_sync(0xffffffffu, s, o);
        float mu = s * (1.0f/64.0f);
        float d0 = a0 - mu, d1 = a1 - mu;
        float vv = d0*d0 + d1*d1;
        #pragma unroll
        for (int o = 16; o > 0; o >>= 1) vv += __shfl_xor_sync(0xffffffffu, vv, o);
        float inv = rsqrtf(vv * (1.0f/64.0f) + 1e-5f);
        float2 x = *reinterpret_cast<const float2*>(g_x + n*64 + 2*lane);
        float h0 = fmaf(d0*inv, lg.x, lb.x) + x.x;
        float h1 = fmaf(d1*inv, lg.y, lb.y) + x.y;
        *reinterpret_cast<float2*>(g_x + n*64 + 2*lane) = make_float2(splusf(h0), splusf(h1));
    }
}

// ---------------- mean pool per graph ----------------
__global__ void pool_prep(){
    int i = blockIdx.x*blockDim.x + threadIdx.x;
    if (i < NGR*64) g_mol[i] = 0.0f;
    if (i < NGR)    g_cnt[i] = 0.0f;
}
__global__ void pool_kernel(const int* __restrict__ batch){
    int lane = threadIdx.x & 31;
    int warp = (blockIdx.x*blockDim.x + threadIdx.x) >> 5;
    int nw   = (gridDim.x*blockDim.x) >> 5;
    for (int n = warp; n < NN; n += nw){
        int g = __ldg(batch + n);
        atomicAdd(&g_mol[g*64 + lane],      g_x[n*64 + lane]);
        atomicAdd(&g_mol[g*64 + lane + 32], g_x[n*64 + lane + 32]);
        if (lane == 0) atomicAdd(&g_cnt[g], 1.0f);
    }
}

// ---------------- fused MLP head ----------------
__global__ void mlp_all(const float* __restrict__ fc1W, const float* __restrict__ fc1b,
                        const float* __restrict__ fcsW, const float* __restrict__ fcsb,
                        const float* __restrict__ outW, const float* __restrict__ outb,
                        float* __restrict__ out){
    __shared__ float buf[2][FCW];
    __shared__ float red[FCW];
    int g = blockIdx.x, j = threadIdx.x;   // 128 threads
    if (j < 64){
        float c = fmaxf(g_cnt[g], 1.0f);
        buf[0][j] = g_mol[g*64 + j] / c;
    }
    __syncthreads();
    float acc = fc1b[j];
    #pragma unroll 4
    for (int f = 0; f < 64; f++) acc = fmaf(buf[0][f], __ldg(fc1W + f*FCW + j), acc);
    buf[1][j] = splusf(acc);
    __syncthreads();
    int cur = 1;
    for (int l = 0; l < 3; l++){
        const float* W = fcsW + l*FCW*FCW;
        float a = fcsb[l*FCW + j];
        #pragma unroll 4
        for (int f = 0; f < FCW; f++) a = fmaf(buf[cur][f], __ldg(W + f*FCW + j), a);
        buf[cur ^ 1][j] = splusf(a);
        cur ^= 1;
        __syncthreads();
    }
    red[j] = buf[cur][j] * __ldg(outW + j);
    __syncthreads();
    for (int o = 64; o > 0; o >>= 1){
        if (j < o) red[j] += red[j + o];
        __syncthreads();
    }
    if (j == 0) out[g] = red[0] + outb[0];
}

// ---------------- launch ----------------
extern "C" void kernel_launch(void* const* d_in, const int* in_sizes, int n_in,
                              void* d_out, int out_size){
    const int*   an    = (const int*)  d_in[0];
    const int*   nbr   = (const int*)  d_in[1];
    const float* dist  = (const float*)d_in[2];
    const int*   batch = (const int*)  d_in[3];
    const float* emb   = (const float*)d_in[4];
    const float* nucW  = (const float*)d_in[5];
    const float* nucb  = (const float*)d_in[6];
    const float* convW = (const float*)d_in[7];
    const float* convb = (const float*)d_in[8];
    const float* bng   = (const float*)d_in[9];
    const float* bnb   = (const float*)d_in[10];
    const float* lng   = (const float*)d_in[11];
    const float* lnb   = (const float*)d_in[12];
    const float* fc1W  = (const float*)d_in[13];
    const float* fc1b  = (const float*)d_in[14];
    const float* fcsW  = (const float*)d_in[15];
    const float* fcsb  = (const float*)d_in[16];
    const float* outW  = (const float*)d_in[17];
    const float* outb  = (const float*)d_in[18];
    float* y = (float*)d_out;

    cudaFuncSetAttribute(gemm_ab,     cudaFuncAttributeMaxDynamicSharedMemorySize, GEMM_SMEM);
    cudaFuncSetAttribute(build_table, cudaFuncAttributeMaxDynamicSharedMemorySize, TAB_SMEM);

    // CSR build (amortized over layers) + initial embedding
    csr_zero<<<80, 256>>>();
    nuc_kernel<<<640, 256>>>(an, emb, nucW, nucb);
    csr_hist<<<640, 256>>>(nbr);
    csr_scan<<<1, 1024>>>();
    csr_scatter<<<640, 256>>>(nbr, dist);

    for (int l = 0; l < NLAYER; l++){
        gemm_ab<<<625, 256, GEMM_SMEM>>>(convW + l*228*128);
        build_table<<<592, 128, TAB_SMEM>>>(convW + l*228*128, convb + l*128);
        edge_pass1<<<640, 256>>>();
        bn_finalize<<<1, 128>>>(bng + l*128, bnb + l*128);
        edge_pass2<<<640, 256>>>(lng + l*64, lnb + l*64);
    }
    pool_prep<<<17, 256>>>();
    pool_kernel<<<640, 256>>>(batch);
    mlp_all<<<NGR, FCW>>>(fc1W, fc1b, fcsW, fcsb, outW, outb, y);
}